// round 11
// baseline (speedup 1.0000x reference)
#include <cuda_runtime.h>
#include <cuda_bf16.h>

#define NN 10
#define DD 64
#define MS 72

__device__ float g_M9[DD][DD];            // out = x @ g_M9 + g_dv9
__device__ float g_dv9[DD];
__device__ volatile unsigned g_flag;      // precompute-done counter (0..33)
__device__ unsigned g_done;               // gemm-block completion counter

__device__ __forceinline__ unsigned tf32_rna(float v) {
    unsigned u = __float_as_uint(v);
    return (u + 0x1000u) & 0xFFFFE000u;
}

__device__ __forceinline__ void mma_tf32(float& c0, float& c1, float& c2, float& c3,
                                         unsigned a0, unsigned a1, unsigned a2, unsigned a3,
                                         unsigned b0, unsigned b1) {
    asm volatile(
        "mma.sync.aligned.m16n8k8.row.col.f32.tf32.tf32.f32 "
        "{%0,%1,%2,%3}, {%4,%5,%6,%7}, {%8,%9}, {%0,%1,%2,%3};"
        : "+f"(c0), "+f"(c1), "+f"(c2), "+f"(c3)
        : "r"(a0), "r"(a1), "r"(a2), "r"(a3), "r"(b0), "r"(b1));
}

// ---- precompute role: blocks 0..32 (unchanged from R8) ----------------------
__device__ void precompute_role(const float* __restrict__ W,
                                const float* __restrict__ B,
                                float* sh, int bi) {
    float* rowsh = sh;                    // [NN][2][DD]
    float* red   = sh + NN * 2 * DD;      // [16][2][DD]
    const int tid  = threadIdx.x;
    const bool bias = (bi == 32);
    const int d0   = bi * 2;
    const int kk   = tid >> 4;
    const int hg   = tid & 15;
    const int rr   = tid >> 6;
    const int hh   = tid & 63;

    if (tid < 128)
        rowsh[(0 * 2 + rr) * DD + hh] = (!bias && (d0 + rr == hh)) ? 1.f : 0.f;
    __syncthreads();

    #pragma unroll
    for (int t = 1; t <= 9; ++t) {
        float extra = 0.f;
        if (tid < 128) {
            if (!bias) {
                extra = W[((size_t)t * DD + (d0 + rr)) * DD + hh];
            } else if (rr == 0) {
                #pragma unroll
                for (int f = 0; f < t; ++f)
                    extra += B[((size_t)f * NN + t) * DD + hh];
            }
        }

        float4 a0 = make_float4(0.f, 0.f, 0.f, 0.f);
        float4 a1 = make_float4(0.f, 0.f, 0.f, 0.f);

        #pragma unroll
        for (int f = 1; f < t; ++f) {
            const float* Wb = W + (((size_t)f * NN + t) * DD + kk * 4) * DD + hg * 4;
            float4 w0 = *reinterpret_cast<const float4*>(Wb + 0 * DD);
            float4 w1 = *reinterpret_cast<const float4*>(Wb + 1 * DD);
            float4 w2 = *reinterpret_cast<const float4*>(Wb + 2 * DD);
            float4 w3 = *reinterpret_cast<const float4*>(Wb + 3 * DD);
            float4 r0 = *reinterpret_cast<const float4*>(&rowsh[(f * 2 + 0) * DD + kk * 4]);
            float4 r1 = *reinterpret_cast<const float4*>(&rowsh[(f * 2 + 1) * DD + kk * 4]);
            a0.x += r0.x * w0.x + r0.y * w1.x + r0.z * w2.x + r0.w * w3.x;
            a0.y += r0.x * w0.y + r0.y * w1.y + r0.z * w2.y + r0.w * w3.y;
            a0.z += r0.x * w0.z + r0.y * w1.z + r0.z * w2.z + r0.w * w3.z;
            a0.w += r0.x * w0.w + r0.y * w1.w + r0.z * w2.w + r0.w * w3.w;
            a1.x += r1.x * w0.x + r1.y * w1.x + r1.z * w2.x + r1.w * w3.x;
            a1.y += r1.x * w0.y + r1.y * w1.y + r1.z * w2.y + r1.w * w3.y;
            a1.z += r1.x * w0.z + r1.y * w1.z + r1.z * w2.z + r1.w * w3.z;
            a1.w += r1.x * w0.w + r1.y * w1.w + r1.z * w2.w + r1.w * w3.w;
        }
        *reinterpret_cast<float4*>(&red[(kk * 2 + 0) * DD + hg * 4]) = a0;
        *reinterpret_cast<float4*>(&red[(kk * 2 + 1) * DD + hg * 4]) = a1;
        __syncthreads();

        if (tid < 128) {
            float s = extra;
            #pragma unroll
            for (int k2 = 0; k2 < 16; ++k2) s += red[(k2 * 2 + rr) * DD + hh];
            rowsh[(t * 2 + rr) * DD + hh] = s;
            if (t == 9) {
                if (!bias)        g_M9[d0 + rr][hh] = s;
                else if (rr == 0) g_dv9[hh] = s;
            }
        }
        __syncthreads();
    }

    __threadfence();
    __syncthreads();
    if (tid == 0) atomicAdd((unsigned*)&g_flag, 1u);
}

// ---- gemm role: blocks 33..288, 256 rows each -------------------------------
__device__ void gemm_role(const float* __restrict__ x, float* __restrict__ out,
                          unsigned* shb, int bid) {
    unsigned* Msm = shb;                                  // [64][MS]
    unsigned* xs  = shb + 64 * MS;                        // [256][MS] tf32 x rows
    float*    dvs = reinterpret_cast<float*>(xs + 256 * MS);
    const int tid  = threadIdx.x;
    const int w    = tid >> 5;
    const int lane = tid & 31;
    const int g    = lane >> 2;
    const int t    = lane & 3;
    const int R0   = bid * 256;

    // ---- pre-wake: COALESCED x load -> tf32 -> conflict-free smem ----
    {
        const float4* xsrc = reinterpret_cast<const float4*>(x + (size_t)R0 * DD);
        #pragma unroll
        for (int i = 0; i < 16; ++i) {
            int c   = i * 256 + tid;                      // float4-chunk id
            int row = c >> 4;                             // 0..255
            int col = (c & 15) * 4;
            float4 v = xsrc[c];                           // nL=4 per instr
            uint4 u = make_uint4(tf32_rna(v.x), tf32_rna(v.y), tf32_rna(v.z), tf32_rna(v.w));
            *reinterpret_cast<uint4*>(&xs[row * MS + col]) = u;
        }
    }

    // ---- wait: single-thread spin, rest park at the barrier ----
    if (tid == 0) {
        while (g_flag < 33u) __nanosleep(64);
        __threadfence();
    }
    __syncthreads();

    // ---- stage M^T + bias ----
    {
        const float* Mflat = &g_M9[0][0];
        #pragma unroll
        for (int i = 0; i < 16; ++i) {
            int idx = i * 256 + tid;                      // coalesced
            int k = idx >> 6, n = idx & 63;
            Msm[n * MS + k] = tf32_rna(Mflat[idx]);
        }
        if (tid < 64) dvs[tid] = g_dv9[tid];
    }
    __syncthreads();

    float2 dvp[8];
    #pragma unroll
    for (int n = 0; n < 8; ++n)
        dvp[n] = *reinterpret_cast<const float2*>(&dvs[8 * n + 2 * t]);

    // ---- mma: warp w owns rows w*32 .. w*32+31 = two m16 tiles ----
    const int rb = w * 32;
    float acc[2][8][4];
    #pragma unroll
    for (int h = 0; h < 2; ++h)
        #pragma unroll
        for (int n = 0; n < 8; ++n)
            #pragma unroll
            for (int c = 0; c < 4; ++c) acc[h][n][c] = 0.f;

    #pragma unroll
    for (int k8 = 0; k8 < 8; ++k8) {
        const int kcol = 8 * k8 + 2 * t;
        uint2 a00 = *reinterpret_cast<const uint2*>(&xs[(rb + g)      * MS + kcol]);
        uint2 a01 = *reinterpret_cast<const uint2*>(&xs[(rb + 8 + g)  * MS + kcol]);
        uint2 a10 = *reinterpret_cast<const uint2*>(&xs[(rb + 16 + g) * MS + kcol]);
        uint2 a11 = *reinterpret_cast<const uint2*>(&xs[(rb + 24 + g) * MS + kcol]);
        #pragma unroll
        for (int n = 0; n < 8; ++n) {
            uint2 bf = *reinterpret_cast<const uint2*>(&Msm[(8 * n + g) * MS + kcol]);
            mma_tf32(acc[0][n][0], acc[0][n][1], acc[0][n][2], acc[0][n][3],
                     a00.x, a01.x, a00.y, a01.y, bf.x, bf.y);
            mma_tf32(acc[1][n][0], acc[1][n][1], acc[1][n][2], acc[1][n][3],
                     a10.x, a11.x, a10.y, a11.y, bf.x, bf.y);
        }
    }

    // ---- epilogue: bias + STS results back into xs (warp-private rows) ----
    float* xsf = reinterpret_cast<float*>(xs);
    #pragma unroll
    for (int h = 0; h < 2; ++h) {
        const int r0 = rb + 16 * h + g;
        #pragma unroll
        for (int n = 0; n < 8; ++n) {
            float2 o0 = make_float2(acc[h][n][0] + dvp[n].x, acc[h][n][1] + dvp[n].y);
            float2 o1 = make_float2(acc[h][n][2] + dvp[n].x, acc[h][n][3] + dvp[n].y);
            *reinterpret_cast<float2*>(&xsf[r0 * MS + 8 * n + 2 * t])       = o0;
            *reinterpret_cast<float2*>(&xsf[(r0 + 8) * MS + 8 * n + 2 * t]) = o1;
        }
    }
    __syncthreads();

    // ---- COALESCED out store ----
    {
        float4* osrc = reinterpret_cast<float4*>(out + (size_t)R0 * DD);
        #pragma unroll
        for (int i = 0; i < 16; ++i) {
            int c   = i * 256 + tid;
            int row = c >> 4;
            int col = (c & 15) * 4;
            float4 v = *reinterpret_cast<const float4*>(&xsf[row * MS + col]);
            osrc[c] = v;                                  // nL=4 per instr
        }
    }

    // ---- replay hygiene: last gemm block resets the counters ----
    __syncthreads();
    if (tid == 0) {
        unsigned v = atomicAdd(&g_done, 1u);
        if (v == 255u) {
            g_done = 0u;
            g_flag = 0u;
            __threadfence();
        }
    }
}

__global__ __launch_bounds__(256, 2) void fused_kernel(const float* __restrict__ x,
                                                       const float* __restrict__ W,
                                                       const float* __restrict__ B,
                                                       float* __restrict__ out) {
    extern __shared__ __align__(16) float sh[];
    if (blockIdx.x < 33)
        precompute_role(W, B, sh, blockIdx.x);
    else
        gemm_role(x, out, reinterpret_cast<unsigned*>(sh), blockIdx.x - 33);
}

extern "C" void kernel_launch(void* const* d_in, const int* in_sizes, int n_in,
                              void* d_out, int out_size) {
    const float* x = (const float*)d_in[0];
    const float* W = (const float*)d_in[1];
    const float* b = (const float*)d_in[2];
    float* out = (float*)d_out;

    const int smem_bytes = (64 * MS + 256 * MS + 64) * 4;   // 92416
    cudaFuncSetAttribute(fused_kernel, cudaFuncAttributeMaxDynamicSharedMemorySize, smem_bytes);

    fused_kernel<<<289, 256, smem_bytes>>>(x, W, b, out);
}

// round 12
// speedup vs baseline: 1.3686x; 1.3686x over previous
#include <cuda_runtime.h>
#include <cuda_bf16.h>

#define NN 10
#define DD 64
#define MS 72
#define PF 4                               // W prefetch depth (matrices)

__device__ float g_M9[DD][DD];            // out = x @ g_M9 + g_dv9
__device__ float g_dv9[DD];
__device__ volatile unsigned g_flag;      // precompute-done counter (0..33)
__device__ unsigned g_done;               // gemm-block completion counter

__device__ __forceinline__ unsigned tf32_rna(float v) {
    unsigned u = __float_as_uint(v);
    return (u + 0x1000u) & 0xFFFFE000u;
}

__device__ __forceinline__ void mma_tf32(float& c0, float& c1, float& c2, float& c3,
                                         unsigned a0, unsigned a1, unsigned a2, unsigned a3,
                                         unsigned b0, unsigned b1) {
    asm volatile(
        "mma.sync.aligned.m16n8k8.row.col.f32.tf32.tf32.f32 "
        "{%0,%1,%2,%3}, {%4,%5,%6,%7}, {%8,%9}, {%0,%1,%2,%3};"
        : "+f"(c0), "+f"(c1), "+f"(c2), "+f"(c3)
        : "r"(a0), "r"(a1), "r"(a2), "r"(a3), "r"(b0), "r"(b1));
}

// ---- precompute role: blocks 0..32, cross-barrier W prefetch ----------------
__device__ void precompute_role(const float* __restrict__ W,
                                const float* __restrict__ B,
                                float* sh, int bi) {
    float* rowsh = sh;                    // [NN][2][DD]
    float* red   = sh + NN * 2 * DD;      // [16][2][DD]
    const int tid  = threadIdx.x;
    const bool bias = (bi == 32);
    const int d0   = bi * 2;
    const int kk   = tid >> 4;            // 0..15: k-rows 4kk..4kk+3
    const int hg   = tid & 15;            // 0..15: h-cols 4hg..4hg+3
    const int rr   = tid >> 6;            // 0..1 (tid < 128)
    const int hh   = tid & 63;

    // prefetched W for the NEXT step, matrices f=1..PF:
    // pw[f-1][r] = W[f, t+1][kk*4 + r][hg*4 .. hg*4+3]
    float4 pw[PF][4];

    if (tid < 128)
        rowsh[(0 * 2 + rr) * DD + hh] = (!bias && (d0 + rr == hh)) ? 1.f : 0.f;
    __syncthreads();

    #pragma unroll
    for (int t = 1; t <= 9; ++t) {
        float extra = 0.f;
        if (tid < 128) {
            if (!bias) {
                extra = W[((size_t)t * DD + (d0 + rr)) * DD + hh];    // W[0,t][d,h]
            } else if (rr == 0) {
                #pragma unroll
                for (int f = 0; f < t; ++f)
                    extra += B[((size_t)f * NN + t) * DD + hh];
            }
        }

        float4 a0 = make_float4(0.f, 0.f, 0.f, 0.f);
        float4 a1 = make_float4(0.f, 0.f, 0.f, 0.f);

        #pragma unroll
        for (int f = 1; f < t; ++f) {
            float4 w0, w1, w2, w3;
            if (f <= PF) {                 // loaded during step t-1, latency hidden
                w0 = pw[f - 1][0]; w1 = pw[f - 1][1];
                w2 = pw[f - 1][2]; w3 = pw[f - 1][3];
            } else {                       // direct load (steps 6..9, f>=5 only)
                const float* Wb = W + (((size_t)f * NN + t) * DD + kk * 4) * DD + hg * 4;
                w0 = *reinterpret_cast<const float4*>(Wb + 0 * DD);
                w1 = *reinterpret_cast<const float4*>(Wb + 1 * DD);
                w2 = *reinterpret_cast<const float4*>(Wb + 2 * DD);
                w3 = *reinterpret_cast<const float4*>(Wb + 3 * DD);
            }
            float4 r0 = *reinterpret_cast<const float4*>(&rowsh[(f * 2 + 0) * DD + kk * 4]);
            float4 r1 = *reinterpret_cast<const float4*>(&rowsh[(f * 2 + 1) * DD + kk * 4]);
            a0.x += r0.x * w0.x + r0.y * w1.x + r0.z * w2.x + r0.w * w3.x;
            a0.y += r0.x * w0.y + r0.y * w1.y + r0.z * w2.y + r0.w * w3.y;
            a0.z += r0.x * w0.z + r0.y * w1.z + r0.z * w2.z + r0.w * w3.z;
            a0.w += r0.x * w0.w + r0.y * w1.w + r0.z * w2.w + r0.w * w3.w;
            a1.x += r1.x * w0.x + r1.y * w1.x + r1.z * w2.x + r1.w * w3.x;
            a1.y += r1.x * w0.y + r1.y * w1.y + r1.z * w2.y + r1.w * w3.y;
            a1.z += r1.x * w0.z + r1.y * w1.z + r1.z * w2.z + r1.w * w3.z;
            a1.w += r1.x * w0.w + r1.y * w1.w + r1.z * w2.w + r1.w * w3.w;
        }

        // ---- issue W prefetch for step t+1 BEFORE the barriers ----
        if (t < 9) {
            #pragma unroll
            for (int f = 1; f <= PF; ++f) {
                if (f <= t) {              // step t+1 needs f = 1..t; cap at PF
                    const float* Wb = W + (((size_t)f * NN + (t + 1)) * DD + kk * 4) * DD + hg * 4;
                    pw[f - 1][0] = *reinterpret_cast<const float4*>(Wb + 0 * DD);
                    pw[f - 1][1] = *reinterpret_cast<const float4*>(Wb + 1 * DD);
                    pw[f - 1][2] = *reinterpret_cast<const float4*>(Wb + 2 * DD);
                    pw[f - 1][3] = *reinterpret_cast<const float4*>(Wb + 3 * DD);
                }
            }
        }

        *reinterpret_cast<float4*>(&red[(kk * 2 + 0) * DD + hg * 4]) = a0;
        *reinterpret_cast<float4*>(&red[(kk * 2 + 1) * DD + hg * 4]) = a1;
        __syncthreads();

        if (tid < 128) {
            float s = extra;
            #pragma unroll
            for (int k2 = 0; k2 < 16; ++k2) s += red[(k2 * 2 + rr) * DD + hh];
            rowsh[(t * 2 + rr) * DD + hh] = s;
            if (t == 9) {
                if (!bias)        g_M9[d0 + rr][hh] = s;
                else if (rr == 0) g_dv9[hh] = s;
            }
        }
        __syncthreads();
    }

    __threadfence();
    __syncthreads();
    if (tid == 0) atomicAdd((unsigned*)&g_flag, 1u);
}

// ---- gemm role: blocks 33..288, 256 rows each (R9 version, unchanged) -------
__device__ void gemm_role(const float* __restrict__ x, float* __restrict__ out,
                          unsigned* shb, int bid) {
    unsigned* Msm = shb;                                  // [64][MS]
    unsigned* xs2 = shb + 64 * MS;                        // [128][MS] tf32 half-2 rows
    float*    dvs = reinterpret_cast<float*>(xs2 + 128 * MS);
    const int tid  = threadIdx.x;
    const int w    = tid >> 5;
    const int lane = tid & 31;
    const int g    = lane >> 2;
    const int t    = lane & 3;
    const int R0   = bid * 256;
    const int rowA = R0 + w * 16 + g;                     // half-1 rows: rowA, rowA+8

    // ---- pre-wake 1: half-1 A fragments into registers (32 regs) ----
    unsigned af1[8][4];
    {
        const float2* a0 = reinterpret_cast<const float2*>(x + (size_t)rowA * DD);
        const float2* a1 = reinterpret_cast<const float2*>(x + (size_t)(rowA + 8) * DD);
        #pragma unroll
        for (int k8 = 0; k8 < 8; ++k8) {
            float2 v0 = a0[4 * k8 + t];
            float2 v1 = a1[4 * k8 + t];
            af1[k8][0] = tf32_rna(v0.x); af1[k8][2] = tf32_rna(v0.y);
            af1[k8][1] = tf32_rna(v1.x); af1[k8][3] = tf32_rna(v1.y);
        }
    }
    // ---- pre-wake 2: half-2 rows tf32-staged into shared (stride MS) ----
    {
        const int r    = tid >> 1;                        // local row 0..127
        const int half = tid & 1;                         // 32-col half
        const float4* src = reinterpret_cast<const float4*>(
            x + (size_t)(R0 + 128 + r) * DD + half * 32);
        #pragma unroll
        for (int i = 0; i < 8; ++i) {
            float4 v = src[i];
            uint4 u = make_uint4(tf32_rna(v.x), tf32_rna(v.y), tf32_rna(v.z), tf32_rna(v.w));
            *reinterpret_cast<uint4*>(&xs2[r * MS + half * 32 + 4 * i]) = u;
        }
    }

    // ---- wait: single-thread spin, rest park at the barrier ----
    if (tid == 0) {
        while (g_flag < 33u) __nanosleep(64);
        __threadfence();
    }
    __syncthreads();

    // ---- stage M^T + bias ----
    {
        const float* Mflat = &g_M9[0][0];
        #pragma unroll
        for (int i = 0; i < 16; ++i) {
            int idx = i * 256 + tid;
            int k = idx >> 6, n = idx & 63;
            Msm[n * MS + k] = tf32_rna(Mflat[idx]);
        }
        if (tid < 64) dvs[tid] = g_dv9[tid];
    }
    __syncthreads();

    float2 dvp[8];
    #pragma unroll
    for (int n = 0; n < 8; ++n)
        dvp[n] = *reinterpret_cast<const float2*>(&dvs[8 * n + 2 * t]);

    // ---- half 1: A from registers ----
    {
        float acc[8][4];
        #pragma unroll
        for (int n = 0; n < 8; ++n)
            #pragma unroll
            for (int c = 0; c < 4; ++c) acc[n][c] = 0.f;
        #pragma unroll
        for (int k8 = 0; k8 < 8; ++k8) {
            const int kcol = 8 * k8 + 2 * t;
            #pragma unroll
            for (int n = 0; n < 8; ++n) {
                uint2 bf = *reinterpret_cast<const uint2*>(&Msm[(8 * n + g) * MS + kcol]);
                mma_tf32(acc[n][0], acc[n][1], acc[n][2], acc[n][3],
                         af1[k8][0], af1[k8][1], af1[k8][2], af1[k8][3], bf.x, bf.y);
            }
        }
        #pragma unroll
        for (int n = 0; n < 8; ++n) {
            float2 o0 = make_float2(acc[n][0] + dvp[n].x, acc[n][1] + dvp[n].y);
            float2 o1 = make_float2(acc[n][2] + dvp[n].x, acc[n][3] + dvp[n].y);
            *reinterpret_cast<float2*>(out + (size_t)rowA * DD + 8 * n + 2 * t)       = o0;
            *reinterpret_cast<float2*>(out + (size_t)(rowA + 8) * DD + 8 * n + 2 * t) = o1;
        }
    }
    // ---- half 2: A fragments from shared (conflict-free LDS.64) ----
    {
        const int lr = w * 16 + g;                        // local rows lr, lr+8
        float acc[8][4];
        #pragma unroll
        for (int n = 0; n < 8; ++n)
            #pragma unroll
            for (int c = 0; c < 4; ++c) acc[n][c] = 0.f;
        #pragma unroll
        for (int k8 = 0; k8 < 8; ++k8) {
            const int kcol = 8 * k8 + 2 * t;
            uint2 a0 = *reinterpret_cast<const uint2*>(&xs2[lr * MS + kcol]);
            uint2 a1 = *reinterpret_cast<const uint2*>(&xs2[(lr + 8) * MS + kcol]);
            #pragma unroll
            for (int n = 0; n < 8; ++n) {
                uint2 bf = *reinterpret_cast<const uint2*>(&Msm[(8 * n + g) * MS + kcol]);
                mma_tf32(acc[n][0], acc[n][1], acc[n][2], acc[n][3],
                         a0.x, a1.x, a0.y, a1.y, bf.x, bf.y);
            }
        }
        const int rowB = R0 + 128 + lr;
        #pragma unroll
        for (int n = 0; n < 8; ++n) {
            float2 o0 = make_float2(acc[n][0] + dvp[n].x, acc[n][1] + dvp[n].y);
            float2 o1 = make_float2(acc[n][2] + dvp[n].x, acc[n][3] + dvp[n].y);
            *reinterpret_cast<float2*>(out + (size_t)rowB * DD + 8 * n + 2 * t)       = o0;
            *reinterpret_cast<float2*>(out + (size_t)(rowB + 8) * DD + 8 * n + 2 * t) = o1;
        }
    }

    // ---- replay hygiene: last gemm block resets the counters ----
    __syncthreads();
    if (tid == 0) {
        unsigned v = atomicAdd(&g_done, 1u);
        if (v == 255u) {
            g_done = 0u;
            g_flag = 0u;
            __threadfence();
        }
    }
}

__global__ __launch_bounds__(256, 2) void fused_kernel(const float* __restrict__ x,
                                                       const float* __restrict__ W,
                                                       const float* __restrict__ B,
                                                       float* __restrict__ out) {
    extern __shared__ __align__(16) float sh[];
    if (blockIdx.x < 33)
        precompute_role(W, B, sh, blockIdx.x);
    else
        gemm_role(x, out, reinterpret_cast<unsigned*>(sh), blockIdx.x - 33);
}

extern "C" void kernel_launch(void* const* d_in, const int* in_sizes, int n_in,
                              void* d_out, int out_size) {
    const float* x = (const float*)d_in[0];
    const float* W = (const float*)d_in[1];
    const float* b = (const float*)d_in[2];
    float* out = (float*)d_out;

    const int smem_bytes = (64 * MS + 128 * MS + 64) * 4;   // 55552
    cudaFuncSetAttribute(fused_kernel, cudaFuncAttributeMaxDynamicSharedMemorySize, smem_bytes);

    fused_kernel<<<289, 256, smem_bytes>>>(x, W, b, out);
}